// round 12
// baseline (speedup 1.0000x reference)
#include <cuda_runtime.h>
#include <math.h>

#define N_POINTS   4194304
#define NUM_LEVELS 16
#define HASH_MASK  ((1u << 19) - 1u)
#define BLOCK      256

// Per-level (res-1) pairs, host-computed with numpy-identical double math,
// passed by value (constant bank; baked into the captured graph).
struct ResParams { float2 rm1[NUM_LEVELS / 2]; };   // [lpair] = (rm1[2l], rm1[2l+1])

__device__ __forceinline__ unsigned hash3(float fx, float fy, float fz, float rm1) {
    return (((unsigned)(fx * rm1))
         ^  ((unsigned)(fy * rm1) * 2654435761u)
         ^  ((unsigned)(fz * rm1) * 805459861u)) & HASH_MASK;
}

// Warp = 8 points; thread = (point sub, level pair); 4 independent gathers.
// Point coords: ONE 96B cooperative LDG + 6 SHFLs. Stores: two coalesced
// 512B STG.128. No divergent cache-policy split: 4 full-warp LDGs (uniform
// .nc) instead of 8 predicated ones — L2 isn't binding, divergence was.
__global__ __launch_bounds__(BLOCK)
void hashenc_kernel(const float*  __restrict__ pts,
                    const float*  __restrict__ tables,
                    float*        __restrict__ out,
                    ResParams rp)
{
    const int t     = threadIdx.x;
    const int lane  = t & 31;
    const int lpair = lane & 7;                  // level pair 0..7
    const int sub   = lane >> 3;                 // point-within-group 0..3
    const int gw    = blockIdx.x * (BLOCK >> 5) + (t >> 5);   // warp id

    const size_t pA = (size_t)gw * 8 + sub;      // group-A point
    const size_t pB = pA + 4;                    // group-B point

    // Cooperative point load: warp's 8 points = 96 contiguous bytes.
    float v = 0.0f;
    if (lane < 24) v = __ldcs(pts + (size_t)gw * 24 + lane);
    const float xA = __shfl_sync(0xffffffffu, v, 3 * sub + 0);
    const float yA = __shfl_sync(0xffffffffu, v, 3 * sub + 1);
    const float zA = __shfl_sync(0xffffffffu, v, 3 * sub + 2);
    const float xB = __shfl_sync(0xffffffffu, v, 12 + 3 * sub + 0);
    const float yB = __shfl_sync(0xffffffffu, v, 12 + 3 * sub + 1);
    const float zB = __shfl_sync(0xffffffffu, v, 12 + 3 * sub + 2);

    // normalize [-1,1] -> [0,1], clamp (matches jnp.clip((p+1)*0.5, 0, 1))
    const float fxA = fminf(fmaxf((xA + 1.0f) * 0.5f, 0.0f), 1.0f);
    const float fyA = fminf(fmaxf((yA + 1.0f) * 0.5f, 0.0f), 1.0f);
    const float fzA = fminf(fmaxf((zA + 1.0f) * 0.5f, 0.0f), 1.0f);
    const float fxB = fminf(fmaxf((xB + 1.0f) * 0.5f, 0.0f), 1.0f);
    const float fyB = fminf(fmaxf((yB + 1.0f) * 0.5f, 0.0f), 1.0f);
    const float fzB = fminf(fmaxf((zB + 1.0f) * 0.5f, 0.0f), 1.0f);

    const float2 rr = rp.rm1[lpair];             // one LDC.64
    const float ra = rr.x, rb = rr.y;
    const int l0 = lpair * 2;

    const float2* tA = reinterpret_cast<const float2*>(tables) + ((size_t)l0 << 19);
    const float2* tB = tA + ((size_t)1 << 19);

    // 4 independent full-warp gathers (uniform policy, no divergence).
    const float2 f0A = __ldg(tA + hash3(fxA, fyA, fzA, ra));
    const float2 f1A = __ldg(tB + hash3(fxA, fyA, fzA, rb));
    const float2 f0B = __ldg(tA + hash3(fxB, fyB, fzB, ra));
    const float2 f1B = __ldg(tB + hash3(fxB, fyB, fzB, rb));

    // Two coalesced 512B warp stores (streaming: output written once).
    float4* ob = reinterpret_cast<float4*>(out);
    __stcs(ob + pA * 8 + lpair, make_float4(f0A.x, f0A.y, f1A.x, f1A.y));
    __stcs(ob + pB * 8 + lpair, make_float4(f0B.x, f0B.y, f1B.x, f1B.y));
}

extern "C" void kernel_launch(void* const* d_in, const int* in_sizes, int n_in,
                              void* d_out, int out_size)
{
    (void)in_sizes; (void)n_in; (void)out_size;

    // numpy-identical resolution computation (double precision, same op order)
    ResParams rp;
    const double l128 = log(128.0);
    float rm1[NUM_LEVELS];
    for (int i = 0; i < NUM_LEVELS; ++i) {
        const int res = (int)floor(16.0 * exp(((double)i * l128) / 15.0));
        rm1[i] = (float)(res - 1);
    }
    for (int p = 0; p < NUM_LEVELS / 2; ++p)
        rp.rm1[p] = make_float2(rm1[2 * p], rm1[2 * p + 1]);

    const float* pts    = (const float*)d_in[0];
    const float* tables = (const float*)d_in[1];
    float*       out    = (float*)d_out;

    // one warp per 8 points -> N_POINTS*4 threads
    const long long total = (long long)N_POINTS * 4;
    hashenc_kernel<<<(unsigned)(total / BLOCK), BLOCK>>>(pts, tables, out, rp);
}

// round 13
// speedup vs baseline: 1.0083x; 1.0083x over previous
#include <cuda_runtime.h>
#include <math.h>

#define N_POINTS   4194304
#define NUM_LEVELS 16
#define HASH_MASK  ((1u << 19) - 1u)
#define BLOCK      512

// Per-level (res-1) pairs, host-computed with numpy-identical double math,
// passed by value (constant bank; baked into the captured graph).
struct ResParams { float2 rm1[NUM_LEVELS / 2]; };   // [lpair] = (rm1[2l], rm1[2l+1])

__device__ __forceinline__ unsigned hash3(float fx, float fy, float fz, float rm1) {
    return (((unsigned)(fx * rm1))
         ^  ((unsigned)(fy * rm1) * 2654435761u)
         ^  ((unsigned)(fz * rm1) * 805459861u)) & HASH_MASK;
}

// Warp = 8 points; thread = (point sub, level pair); 4 independent full-warp
// gathers (uniform cache policy — L1 hit/miss costs the same wavefront, only
// distinct-line count matters and it's irreducible for hashed 8B lookups).
// Point coords: ONE 96B cooperative LDG (.ca: line shared with next warp)
// + 6 SHFLs. Stores: two coalesced 512B STG.128, streaming.
__global__ __launch_bounds__(BLOCK)
void hashenc_kernel(const float*  __restrict__ pts,
                    const float*  __restrict__ tables,
                    float*        __restrict__ out,
                    ResParams rp)
{
    const int t     = threadIdx.x;
    const int lane  = t & 31;
    const int lpair = lane & 7;                  // level pair 0..7
    const int sub   = lane >> 3;                 // point-within-group 0..3
    const int gw    = blockIdx.x * (BLOCK >> 5) + (t >> 5);   // warp id

    const size_t pA = (size_t)gw * 8 + sub;      // group-A point
    const size_t pB = pA + 4;                    // group-B point

    // Cooperative point load: warp's 8 points = 96 contiguous bytes.
    // Default caching: the 128B line is partially reused by the adjacent warp.
    float v = 0.0f;
    if (lane < 24) v = __ldg(pts + (size_t)gw * 24 + lane);
    const float xA = __shfl_sync(0xffffffffu, v, 3 * sub + 0);
    const float yA = __shfl_sync(0xffffffffu, v, 3 * sub + 1);
    const float zA = __shfl_sync(0xffffffffu, v, 3 * sub + 2);
    const float xB = __shfl_sync(0xffffffffu, v, 12 + 3 * sub + 0);
    const float yB = __shfl_sync(0xffffffffu, v, 12 + 3 * sub + 1);
    const float zB = __shfl_sync(0xffffffffu, v, 12 + 3 * sub + 2);

    // normalize [-1,1] -> [0,1], clamp (matches jnp.clip((p+1)*0.5, 0, 1))
    const float fxA = fminf(fmaxf((xA + 1.0f) * 0.5f, 0.0f), 1.0f);
    const float fyA = fminf(fmaxf((yA + 1.0f) * 0.5f, 0.0f), 1.0f);
    const float fzA = fminf(fmaxf((zA + 1.0f) * 0.5f, 0.0f), 1.0f);
    const float fxB = fminf(fmaxf((xB + 1.0f) * 0.5f, 0.0f), 1.0f);
    const float fyB = fminf(fmaxf((yB + 1.0f) * 0.5f, 0.0f), 1.0f);
    const float fzB = fminf(fmaxf((zB + 1.0f) * 0.5f, 0.0f), 1.0f);

    const float2 rr = rp.rm1[lpair];             // one LDC.64
    const float ra = rr.x, rb = rr.y;
    const int l0 = lpair * 2;

    const float2* tA = reinterpret_cast<const float2*>(tables) + ((size_t)l0 << 19);
    const float2* tB = tA + ((size_t)1 << 19);

    // 4 independent full-warp gathers.
    const float2 f0A = __ldg(tA + hash3(fxA, fyA, fzA, ra));
    const float2 f1A = __ldg(tB + hash3(fxA, fyA, fzA, rb));
    const float2 f0B = __ldg(tA + hash3(fxB, fyB, fzB, ra));
    const float2 f1B = __ldg(tB + hash3(fxB, fyB, fzB, rb));

    // Two coalesced 512B warp stores (streaming: output written once).
    float4* ob = reinterpret_cast<float4*>(out);
    __stcs(ob + pA * 8 + lpair, make_float4(f0A.x, f0A.y, f1A.x, f1A.y));
    __stcs(ob + pB * 8 + lpair, make_float4(f0B.x, f0B.y, f1B.x, f1B.y));
}

extern "C" void kernel_launch(void* const* d_in, const int* in_sizes, int n_in,
                              void* d_out, int out_size)
{
    (void)in_sizes; (void)n_in; (void)out_size;

    // numpy-identical resolution computation (double precision, same op order)
    ResParams rp;
    const double l128 = log(128.0);
    float rm1[NUM_LEVELS];
    for (int i = 0; i < NUM_LEVELS; ++i) {
        const int res = (int)floor(16.0 * exp(((double)i * l128) / 15.0));
        rm1[i] = (float)(res - 1);
    }
    for (int p = 0; p < NUM_LEVELS / 2; ++p)
        rp.rm1[p] = make_float2(rm1[2 * p], rm1[2 * p + 1]);

    const float* pts    = (const float*)d_in[0];
    const float* tables = (const float*)d_in[1];
    float*       out    = (float*)d_out;

    // one warp per 8 points -> N_POINTS*4 threads
    const long long total = (long long)N_POINTS * 4;
    hashenc_kernel<<<(unsigned)(total / BLOCK), BLOCK>>>(pts, tables, out, rp);
}